// round 12
// baseline (speedup 1.0000x reference)
#include <cuda_runtime.h>
#include <cstdint>
#include <cstddef>

typedef unsigned long long ull;

#define T_STEPS 2048
#define HDIM 32
#define DIN 6
#define WARPS_PER_CTA 4
#define CHUNK 64
#define NCHUNK (T_STEPS / CHUNK)

// Compiler-only memory fence (no instruction). Used ONLY at x-chunk staging
// boundaries; per-iteration ordering is guaranteed by per-thread aliasing
// (each lane's h-vector load overlaps its own store) + warp in-order smem.
#define CBAR() asm volatile("" ::: "memory")

__device__ __forceinline__ ull fma2(ull a, ull b, ull c) {
    ull r;
    asm("fma.rn.f32x2 %0, %1, %2, %3;" : "=l"(r) : "l"(a), "l"(b), "l"(c));
    return r;
}
__device__ __forceinline__ ull add2(ull a, ull b) {
    ull r;
    asm("add.rn.f32x2 %0, %1, %2;" : "=l"(r) : "l"(a), "l"(b));
    return r;
}
__device__ __forceinline__ float hsum2(ull a) {
    float lo, hi;
    asm("mov.b64 {%0, %1}, %2;" : "=f"(lo), "=f"(hi) : "l"(a));
    return lo + hi;
}
__device__ __forceinline__ ull pack2(float lo, float hi) {
    ull r;
    asm("mov.b64 %0, {%1, %2};" : "=l"(r) : "f"(lo), "f"(hi));
    return r;
}
// single-instruction MUFU.TANH
__device__ __forceinline__ float tanh_mufu(float x) {
    float r;
    asm("tanh.approx.f32 %0, %1;" : "=f"(r) : "f"(x));
    return r;
}

// RNN cell (layers 1,2): tanh( Wp . hin + Wr . hprev + bias ), bias folded into a0 init
__device__ __forceinline__ float cell(const ull (&wp)[16], const float* hin,
                                      const ull (&wr)[16], const float* hprev,
                                      ull biasp) {
    ull a0 = biasp, a1 = 0ull, a2 = 0ull, a3 = 0ull;
    const ulonglong2* hp = reinterpret_cast<const ulonglong2*>(hin);
    const ulonglong2* hr = reinterpret_cast<const ulonglong2*>(hprev);
#pragma unroll
    for (int p = 0; p < 8; p++) {
        ulonglong2 u = hp[p];           // LDS.128 broadcast: h[4p..4p+3]
        a0 = fma2(u.x, wp[2 * p],     a0);
        a1 = fma2(u.y, wp[2 * p + 1], a1);
        ulonglong2 v = hr[p];
        a2 = fma2(v.x, wr[2 * p],     a2);
        a3 = fma2(v.y, wr[2 * p + 1], a3);
    }
    a0 = add2(add2(a0, a1), add2(a2, a3));
    return tanh_mufu(hsum2(a0));
}

// layer-0 cell: x-projection (D=6 -> 3 pairs) + recurrence, bias folded
__device__ __forceinline__ float cell0(const ull (&wx)[3], const float* xp,
                                       const ull (&wr)[16], const float* hprev,
                                       ull biasp) {
    const ull* xq = reinterpret_cast<const ull*>(xp);   // 8B-aligned pairs
    ull a0 = fma2(xq[0], wx[0], biasp);
    a0 = fma2(xq[1], wx[1], a0);
    a0 = fma2(xq[2], wx[2], a0);
    ull a1 = 0ull, a2 = 0ull;
    const ulonglong2* hr = reinterpret_cast<const ulonglong2*>(hprev);
#pragma unroll
    for (int p = 0; p < 8; p++) {
        ulonglong2 v = hr[p];
        a1 = fma2(v.x, wr[2 * p],     a1);
        a2 = fma2(v.y, wr[2 * p + 1], a2);
    }
    a0 = add2(a0, add2(a1, a2));
    return tanh_mufu(hsum2(a0));
}

__global__ void __launch_bounds__(WARPS_PER_CTA * 32, 1)
rnn3_fused_kernel(const float* __restrict__ x,
                  const float* __restrict__ Wih0,
                  const float* __restrict__ WihR,
                  const float* __restrict__ Whh,
                  const float* __restrict__ bih,
                  const float* __restrict__ bhh,
                  const float* __restrict__ fcw,
                  const float* __restrict__ fcb,
                  float* __restrict__ out) {
    __shared__ __align__(16) float hb[WARPS_PER_CTA][3][2][HDIM];       // [warp][layer][parity][h]
    __shared__ __align__(16) float xs[WARPS_PER_CTA][2][CHUNK * DIN];   // x staging, double buffered

    const int tid = threadIdx.x;
    const int w = tid >> 5;
    const int j = tid & 31;
    const int b = blockIdx.x * WARPS_PER_CTA + w;

    // zero h state (both parities)
    for (int q = tid; q < WARPS_PER_CTA * 3 * 2 * HDIM; q += WARPS_PER_CTA * 32)
        (&hb[0][0][0][0])[q] = 0.0f;
    __syncthreads();

    // ---- load weights into per-lane registers as packed f32x2 pairs ----
    ull wx0[3], wr0[16], wp1[16], wr1[16], wp2[16], wr2[16];
    {
        const ull* q = reinterpret_cast<const ull*>(Wih0 + j * DIN);    // j*24B: 8B aligned
        wx0[0] = q[0]; wx0[1] = q[1]; wx0[2] = q[2];
    }
    {
        const ull* q0 = reinterpret_cast<const ull*>(Whh  + (0 * HDIM + j) * HDIM);
        const ull* q1 = reinterpret_cast<const ull*>(Whh  + (1 * HDIM + j) * HDIM);
        const ull* q2 = reinterpret_cast<const ull*>(Whh  + (2 * HDIM + j) * HDIM);
        const ull* p1 = reinterpret_cast<const ull*>(WihR + (0 * HDIM + j) * HDIM);
        const ull* p2 = reinterpret_cast<const ull*>(WihR + (1 * HDIM + j) * HDIM);
#pragma unroll
        for (int k = 0; k < 16; k++) {
            wr0[k] = q0[k]; wr1[k] = q1[k]; wr2[k] = q2[k];
            wp1[k] = p1[k]; wp2[k] = p2[k];
        }
    }
    const ull bp0 = pack2(bih[0 * HDIM + j] + bhh[0 * HDIM + j], 0.0f);
    const ull bp1 = pack2(bih[1 * HDIM + j] + bhh[1 * HDIM + j], 0.0f);
    const ull bp2 = pack2(bih[2 * HDIM + j] + bhh[2 * HDIM + j], 0.0f);

    float* h0 = &hb[w][0][0][0];
    float* h1 = &hb[w][1][0][0];
    float* h2 = &hb[w][2][0][0];

    // ---- x staging: chunk 0 direct, chunk 1 prefetched into registers ----
    const float4* gx = reinterpret_cast<const float4*>(x + (size_t)b * (T_STEPS * DIN));
    float4* xs0 = reinterpret_cast<float4*>(&xs[w][0][0]);
    float4* xs1 = reinterpret_cast<float4*>(&xs[w][1][0]);

    xs0[j] = gx[j]; xs0[j + 32] = gx[j + 32]; xs0[j + 64] = gx[j + 64];
    CBAR();
    float4 pf0 = gx[96 + j], pf1 = gx[96 + j + 32], pf2 = gx[96 + j + 64];

    float h2last = 0.0f;

    // one skewed iteration: L0 at t=i, L1 at t=i-1, L2 at t=i-2.
    // KEY: each h is STORED IMMEDIATELY after its cell computes it, so the
    // next iteration's dependent loads have ~2 cells (~200cyc) of independent
    // instructions above them to be hoisted into by ptxas within the unroll
    // window. No later cell in the same iteration reads a region written
    // earlier in the iteration, so this ordering is semantically identical.
    auto iter = [&](int pw, const float* xp) {
        const int pr = pw ^ 1;
        float n0 = cell0(wx0, xp, wr0, h0 + pr * HDIM, bp0);
        h0[pw * HDIM + j] = n0;                               // store ASAP
        float n1 = cell(wp1, h0 + pr * HDIM, wr1, h1 + pw * HDIM, bp1);
        h1[pr * HDIM + j] = n1;                               // store ASAP
        float n2 = cell(wp2, h1 + pw * HDIM, wr2, h2 + pr * HDIM, bp2);
        h2[pw * HDIM + j] = n2;
    };

    // ---- prologue peels ----
    {   // i = 0: only L0(0); h0[-1]=0 (parity 1 zeroed)
        float n0 = cell0(wx0, &xs[w][0][0 * DIN], wr0, h0 + HDIM, bp0);
        h0[j] = n0;
    }
    {   // i = 1: L0(1) + L1(0); h1[-1]=0 (parity 1 zeroed)
        float n0 = cell0(wx0, &xs[w][0][1 * DIN], wr0, h0, bp0);
        h0[HDIM + j] = n0;
        float n1 = cell(wp1, h0, wr1, h1 + HDIM, bp1);
        h1[j] = n1;
    }

    // ---- chunk 0 (cold): i = 2 .. 63 ----
#pragma unroll 1
    for (int s = 2; s < CHUNK; s += 2) {
        iter(0, &xs[w][0][s * DIN]);
        iter(1, &xs[w][0][(s + 1) * DIN]);
    }

    // ---- main chunks 1 .. NCHUNK-1 (hot, unrolled x4 for cross-iter pipelining) ----
#pragma unroll 1
    for (int c = 1; c < NCHUNK; c++) {
        {   // stage chunk c from prefetch regs, prefetch chunk c+1
            float4* dst = (c & 1) ? xs1 : xs0;
            dst[j] = pf0; dst[j + 32] = pf1; dst[j + 64] = pf2;
            CBAR();
            if (c < NCHUNK - 1) {
                pf0 = gx[(c + 1) * 96 + j];
                pf1 = gx[(c + 1) * 96 + j + 32];
                pf2 = gx[(c + 1) * 96 + j + 64];
            }
        }
        const float* xrow = (c & 1) ? &xs[w][1][0] : &xs[w][0][0];
#pragma unroll 4
        for (int s = 0; s < CHUNK; s += 2) {
            iter(0, xrow + s * DIN);            // even global t
            iter(1, xrow + (s + 1) * DIN);      // odd global t
        }
        CBAR();                                  // don't float next chunk's staging stores up
    }

    // ---- epilogue peels ----
    {   // i = 2048 (pw=0, pr=1): L1(2047) + L2(2046)
        float n1 = cell(wp1, h0 + HDIM, wr1, h1,        bp1);
        h1[HDIM + j] = n1;
        float n2 = cell(wp2, h1,        wr2, h2 + HDIM, bp2);
        h2[j] = n2;
    }
    {   // i = 2049 (pw=1, pr=0): L2(2047) -> final hidden state, keep in register
        h2last = cell(wp2, h1 + HDIM, wr2, h2, bp2);
    }

    // ---- FC head: out[b,c] = sum_j h2last_j * fcw[c,j] + fcb[c] ----
    float s0v = h2last * fcw[0 * HDIM + j];
    float s1v = h2last * fcw[1 * HDIM + j];
    float s2v = h2last * fcw[2 * HDIM + j];
    float s3v = h2last * fcw[3 * HDIM + j];
    float s4v = h2last * fcw[4 * HDIM + j];
    float s5v = h2last * fcw[5 * HDIM + j];
#pragma unroll
    for (int off = 16; off; off >>= 1) {
        s0v += __shfl_xor_sync(0xffffffffu, s0v, off);
        s1v += __shfl_xor_sync(0xffffffffu, s1v, off);
        s2v += __shfl_xor_sync(0xffffffffu, s2v, off);
        s3v += __shfl_xor_sync(0xffffffffu, s3v, off);
        s4v += __shfl_xor_sync(0xffffffffu, s4v, off);
        s5v += __shfl_xor_sync(0xffffffffu, s5v, off);
    }
    float v = s0v;
    if (j == 1) v = s1v;
    if (j == 2) v = s2v;
    if (j == 3) v = s3v;
    if (j == 4) v = s4v;
    if (j == 5) v = s5v;
    if (j < 6) out[b * 6 + j] = v + fcb[j];
}

extern "C" void kernel_launch(void* const* d_in, const int* in_sizes, int n_in,
                              void* d_out, int out_size) {
    const float* x    = (const float*)d_in[0];
    const float* Wih0 = (const float*)d_in[1];
    const float* WihR = (const float*)d_in[2];
    const float* Whh  = (const float*)d_in[3];
    const float* bih  = (const float*)d_in[4];
    const float* bhh  = (const float*)d_in[5];
    const float* fcw  = (const float*)d_in[6];
    const float* fcb  = (const float*)d_in[7];

    const int B = in_sizes[0] / (T_STEPS * DIN);   // 512
    rnn3_fused_kernel<<<B / WARPS_PER_CTA, WARPS_PER_CTA * 32>>>(
        x, Wih0, WihR, Whh, bih, bhh, fcw, fcb, (float*)d_out);
}

// round 13
// speedup vs baseline: 1.6385x; 1.6385x over previous
#include <cuda_runtime.h>
#include <cstdint>
#include <cstddef>

typedef unsigned long long ull;

#define T_STEPS 2048
#define HDIM 32
#define DIN 6
#define WARPS_PER_CTA 4
#define CHUNK 64
#define NCHUNK (T_STEPS / CHUNK)

#define CBAR() asm volatile("" ::: "memory")

__device__ __forceinline__ ull fma2(ull a, ull b, ull c) {
    ull r;
    asm("fma.rn.f32x2 %0, %1, %2, %3;" : "=l"(r) : "l"(a), "l"(b), "l"(c));
    return r;
}
__device__ __forceinline__ ull add2(ull a, ull b) {
    ull r;
    asm("add.rn.f32x2 %0, %1, %2;" : "=l"(r) : "l"(a), "l"(b));
    return r;
}
__device__ __forceinline__ float hsum2(ull a) {
    float lo, hi;
    asm("mov.b64 {%0, %1}, %2;" : "=f"(lo), "=f"(hi) : "l"(a));
    return lo + hi;
}
__device__ __forceinline__ ull pack2(float lo, float hi) {
    ull r;
    asm("mov.b64 %0, {%1, %2};" : "=l"(r) : "f"(lo), "f"(hi));
    return r;
}
__device__ __forceinline__ float tanh_mufu(float x) {
    float r;
    asm("tanh.approx.f32 %0, %1;" : "=f"(r) : "f"(x));
    return r;
}

// RNN cell (layers 1,2): tanh( Wp . hin + Wr . hprev + bias ), bias folded into a0 init
__device__ __forceinline__ float cell(const ull (&wp)[16], const float* hin,
                                      const ull (&wr)[16], const float* hprev,
                                      ull biasp) {
    ull a0 = biasp, a1 = 0ull, a2 = 0ull, a3 = 0ull;
    const ulonglong2* hp = reinterpret_cast<const ulonglong2*>(hin);
    const ulonglong2* hr = reinterpret_cast<const ulonglong2*>(hprev);
#pragma unroll
    for (int p = 0; p < 8; p++) {
        ulonglong2 u = hp[p];           // LDS.128 broadcast
        a0 = fma2(u.x, wp[2 * p],     a0);
        a1 = fma2(u.y, wp[2 * p + 1], a1);
        ulonglong2 v = hr[p];
        a2 = fma2(v.x, wr[2 * p],     a2);
        a3 = fma2(v.y, wr[2 * p + 1], a3);
    }
    a0 = add2(add2(a0, a1), add2(a2, a3));
    return tanh_mufu(hsum2(a0));
}

// layer-0 cell: x-projection (D=6 -> 3 pairs) + recurrence, bias folded
__device__ __forceinline__ float cell0(const ull (&wx)[3], const float* xp,
                                       const ull (&wr)[16], const float* hprev,
                                       ull biasp) {
    const ull* xq = reinterpret_cast<const ull*>(xp);   // 8B-aligned pairs
    ull a0 = fma2(xq[0], wx[0], biasp);
    a0 = fma2(xq[1], wx[1], a0);
    a0 = fma2(xq[2], wx[2], a0);
    ull a1 = 0ull, a2 = 0ull;
    const ulonglong2* hr = reinterpret_cast<const ulonglong2*>(hprev);
#pragma unroll
    for (int p = 0; p < 8; p++) {
        ulonglong2 v = hr[p];
        a1 = fma2(v.x, wr[2 * p],     a1);
        a2 = fma2(v.y, wr[2 * p + 1], a2);
    }
    a0 = add2(a0, add2(a1, a2));
    return tanh_mufu(hsum2(a0));
}

__global__ void __launch_bounds__(WARPS_PER_CTA * 32, 1)
rnn3_fused_kernel(const float* __restrict__ x,
                  const float* __restrict__ Wih0,
                  const float* __restrict__ WihR,
                  const float* __restrict__ Whh,
                  const float* __restrict__ bih,
                  const float* __restrict__ bhh,
                  const float* __restrict__ fcw,
                  const float* __restrict__ fcb,
                  float* __restrict__ out) {
    // Six DISTINCT shared objects (layer x parity): distinct objects cannot
    // alias, so a store to one never fences loads from another. This lets
    // store-ASAP + unroll expose the skew as a software pipeline.
    __shared__ __align__(16) float h0E[WARPS_PER_CTA][HDIM];
    __shared__ __align__(16) float h0O[WARPS_PER_CTA][HDIM];
    __shared__ __align__(16) float h1E[WARPS_PER_CTA][HDIM];
    __shared__ __align__(16) float h1O[WARPS_PER_CTA][HDIM];
    __shared__ __align__(16) float h2E[WARPS_PER_CTA][HDIM];
    __shared__ __align__(16) float h2O[WARPS_PER_CTA][HDIM];
    __shared__ __align__(16) float xs[WARPS_PER_CTA][2][CHUNK * DIN];

    const int tid = threadIdx.x;
    const int w = tid >> 5;
    const int j = tid & 31;
    const int b = blockIdx.x * WARPS_PER_CTA + w;

    // zero all h state
    h0E[w][j] = 0.0f; h0O[w][j] = 0.0f;
    h1E[w][j] = 0.0f; h1O[w][j] = 0.0f;
    h2E[w][j] = 0.0f; h2O[w][j] = 0.0f;
    __syncthreads();

    // ---- weights in registers as packed f32x2 pairs ----
    ull wx0[3], wr0[16], wp1[16], wr1[16], wp2[16], wr2[16];
    {
        const ull* q = reinterpret_cast<const ull*>(Wih0 + j * DIN);
        wx0[0] = q[0]; wx0[1] = q[1]; wx0[2] = q[2];
    }
    {
        const ull* q0 = reinterpret_cast<const ull*>(Whh  + (0 * HDIM + j) * HDIM);
        const ull* q1 = reinterpret_cast<const ull*>(Whh  + (1 * HDIM + j) * HDIM);
        const ull* q2 = reinterpret_cast<const ull*>(Whh  + (2 * HDIM + j) * HDIM);
        const ull* p1 = reinterpret_cast<const ull*>(WihR + (0 * HDIM + j) * HDIM);
        const ull* p2 = reinterpret_cast<const ull*>(WihR + (1 * HDIM + j) * HDIM);
#pragma unroll
        for (int k = 0; k < 16; k++) {
            wr0[k] = q0[k]; wr1[k] = q1[k]; wr2[k] = q2[k];
            wp1[k] = p1[k]; wp2[k] = p2[k];
        }
    }
    const ull bp0 = pack2(bih[0 * HDIM + j] + bhh[0 * HDIM + j], 0.0f);
    const ull bp1 = pack2(bih[1 * HDIM + j] + bhh[1 * HDIM + j], 0.0f);
    const ull bp2 = pack2(bih[2 * HDIM + j] + bhh[2 * HDIM + j], 0.0f);

    // ---- x staging: chunk 0 direct, chunk 1 prefetched into registers ----
    const float4* gx = reinterpret_cast<const float4*>(x + (size_t)b * (T_STEPS * DIN));
    float4* xs0 = reinterpret_cast<float4*>(&xs[w][0][0]);
    float4* xs1 = reinterpret_cast<float4*>(&xs[w][1][0]);

    xs0[j] = gx[j]; xs0[j + 32] = gx[j + 32]; xs0[j + 64] = gx[j + 64];
    CBAR();
    float4 pf0 = gx[96 + j], pf1 = gx[96 + j + 32], pf2 = gx[96 + j + 64];

    float h2last = 0.0f;

    // Skewed iteration, even timestep (pw=0, pr=1):
    //   L0 reads h0O, writes h0E; L1 reads h0O,h1E, writes h1O; L2 reads h1E,h2O, writes h2E.
    // Every array is read-only or write-only per iteration; stores issue ASAP.
    auto iterE = [&](const float* xp) {
        float n0 = cell0(wx0, xp, wr0, &h0O[w][0], bp0);
        h0E[w][j] = n0;
        float n1 = cell(wp1, &h0O[w][0], wr1, &h1E[w][0], bp1);
        h1O[w][j] = n1;
        float n2 = cell(wp2, &h1E[w][0], wr2, &h2O[w][0], bp2);
        h2E[w][j] = n2;
    };
    // odd timestep (pw=1, pr=0): parities swapped
    auto iterO = [&](const float* xp) {
        float n0 = cell0(wx0, xp, wr0, &h0E[w][0], bp0);
        h0O[w][j] = n0;
        float n1 = cell(wp1, &h0E[w][0], wr1, &h1O[w][0], bp1);
        h1E[w][j] = n1;
        float n2 = cell(wp2, &h1O[w][0], wr2, &h2E[w][0], bp2);
        h2O[w][j] = n2;
    };

    // ---- prologue peels ----
    {   // i = 0 (pw=0): only L0; h0[-1] = h0O = zeros
        float n0 = cell0(wx0, &xs[w][0][0 * DIN], wr0, &h0O[w][0], bp0);
        h0E[w][j] = n0;
    }
    {   // i = 1 (pw=1): L0 + L1; h1[pw=1] = h1O = zeros
        float n0 = cell0(wx0, &xs[w][0][1 * DIN], wr0, &h0E[w][0], bp0);
        h0O[w][j] = n0;
        float n1 = cell(wp1, &h0E[w][0], wr1, &h1O[w][0], bp1);
        h1E[w][j] = n1;
    }

    // ---- chunk 0 (cold): i = 2 .. 63 ----
#pragma unroll 1
    for (int s = 2; s < CHUNK; s += 2) {
        iterE(&xs[w][0][s * DIN]);
        iterO(&xs[w][0][(s + 1) * DIN]);
    }

    // ---- main chunks 1 .. NCHUNK-1 (hot, unrolled x4) ----
#pragma unroll 1
    for (int c = 1; c < NCHUNK; c++) {
        {   // stage chunk c from prefetch regs, prefetch chunk c+1
            float4* dst = (c & 1) ? xs1 : xs0;
            dst[j] = pf0; dst[j + 32] = pf1; dst[j + 64] = pf2;
            CBAR();
            if (c < NCHUNK - 1) {
                pf0 = gx[(c + 1) * 96 + j];
                pf1 = gx[(c + 1) * 96 + j + 32];
                pf2 = gx[(c + 1) * 96 + j + 64];
            }
        }
        const float* xrow = (c & 1) ? &xs[w][1][0] : &xs[w][0][0];
#pragma unroll 4
        for (int s = 0; s < CHUNK; s += 2) {
            iterE(xrow + s * DIN);              // even global t
            iterO(xrow + (s + 1) * DIN);        // odd global t
        }
        CBAR();                                  // keep next chunk's staging stores below
    }

    // ---- epilogue peels ----
    {   // i = 2048 (pw=0, pr=1): L1(2047) + L2(2046)
        float n1 = cell(wp1, &h0O[w][0], wr1, &h1E[w][0], bp1);
        h1O[w][j] = n1;
        float n2 = cell(wp2, &h1E[w][0], wr2, &h2O[w][0], bp2);
        h2E[w][j] = n2;
    }
    {   // i = 2049 (pw=1, pr=0): L2(2047) -> final hidden state, keep in register
        h2last = cell(wp2, &h1O[w][0], wr2, &h2E[w][0], bp2);
    }

    // ---- FC head: out[b,c] = sum_j h2last_j * fcw[c,j] + fcb[c] ----
    float s0v = h2last * fcw[0 * HDIM + j];
    float s1v = h2last * fcw[1 * HDIM + j];
    float s2v = h2last * fcw[2 * HDIM + j];
    float s3v = h2last * fcw[3 * HDIM + j];
    float s4v = h2last * fcw[4 * HDIM + j];
    float s5v = h2last * fcw[5 * HDIM + j];
#pragma unroll
    for (int off = 16; off; off >>= 1) {
        s0v += __shfl_xor_sync(0xffffffffu, s0v, off);
        s1v += __shfl_xor_sync(0xffffffffu, s1v, off);
        s2v += __shfl_xor_sync(0xffffffffu, s2v, off);
        s3v += __shfl_xor_sync(0xffffffffu, s3v, off);
        s4v += __shfl_xor_sync(0xffffffffu, s4v, off);
        s5v += __shfl_xor_sync(0xffffffffu, s5v, off);
    }
    float v = s0v;
    if (j == 1) v = s1v;
    if (j == 2) v = s2v;
    if (j == 3) v = s3v;
    if (j == 4) v = s4v;
    if (j == 5) v = s5v;
    if (j < 6) out[b * 6 + j] = v + fcb[j];
}

extern "C" void kernel_launch(void* const* d_in, const int* in_sizes, int n_in,
                              void* d_out, int out_size) {
    const float* x    = (const float*)d_in[0];
    const float* Wih0 = (const float*)d_in[1];
    const float* WihR = (const float*)d_in[2];
    const float* Whh  = (const float*)d_in[3];
    const float* bih  = (const float*)d_in[4];
    const float* bhh  = (const float*)d_in[5];
    const float* fcw  = (const float*)d_in[6];
    const float* fcb  = (const float*)d_in[7];

    const int B = in_sizes[0] / (T_STEPS * DIN);   // 512
    rnn3_fused_kernel<<<B / WARPS_PER_CTA, WARPS_PER_CTA * 32>>>(
        x, Wih0, WihR, Whh, bih, bhh, fcw, fcb, (float*)d_out);
}